// round 1
// baseline (speedup 1.0000x reference)
#include <cuda_runtime.h>
#include <math.h>

// Problem constants (from reference)
#define DIM     300
#define D4      75            // DIM / 4 floats per float4
#define BATCH   8192
#define N_OUT   20            // 2*WINDOW positives
#define N_NEG   50            // 2*WINDOW*NEG negatives
#define N_ROWS  70            // N_OUT + N_NEG
#define THREADS 256
#define NWARPS  (THREADS / 32)

// Scratch for per-block partials (no cudaMalloc allowed)
__device__ float g_partial[BATCH];

__device__ __forceinline__ float log_sigmoid_f(float x) {
    // stable: x>0 -> -log1p(exp(-x)); x<=0 -> x - log1p(exp(x))
    float ax = fabsf(x);
    float l  = -log1pf(__expf(-ax));
    return x > 0.0f ? l : x + l;
}

__global__ __launch_bounds__(THREADS)
void w2v_loss_kernel(const float* __restrict__ i_emb,
                     const float* __restrict__ o_emb,
                     const int*   __restrict__ i_word,
                     const int*   __restrict__ o_word,
                     const int*   __restrict__ n_word)
{
    __shared__ float4 s_iv[D4];
    __shared__ float  s_warp[NWARPS];

    const int b    = blockIdx.x;
    const int tid  = threadIdx.x;
    const int lane = tid & 31;
    const int w    = tid >> 5;

    // Gather i_vec into shared (75 float4 = 300 floats, 16B-aligned: 300*4=1200)
    const int iw = i_word[b];
    const float4* iv_row = reinterpret_cast<const float4*>(i_emb + (size_t)iw * DIM);
    if (tid < D4) s_iv[tid] = iv_row[tid];
    __syncthreads();

    const int* ow = o_word + (size_t)b * N_OUT;
    const int* nw = n_word + (size_t)b * N_NEG;

    float acc = 0.0f;

    // Each warp handles rows w, w+8, w+16, ... (< 70)
    for (int r = w; r < N_ROWS; r += NWARPS) {
        const bool is_pos = (r < N_OUT);
        const int idx = is_pos ? ow[r] : nw[r - N_OUT];
        const float4* row = reinterpret_cast<const float4*>(o_emb + (size_t)idx * DIM);

        // Front-batched loads for MLP: 3 independent LDG.128 per lane
        float4 a0 = row[lane];
        float4 a1 = row[lane + 32];
        float4 a2 = make_float4(0.f, 0.f, 0.f, 0.f);
        if (lane < (D4 - 64)) a2 = row[lane + 64];   // lanes 0..10

        float4 b0 = s_iv[lane];
        float4 b1 = s_iv[lane + 32];
        float4 b2 = make_float4(0.f, 0.f, 0.f, 0.f);
        if (lane < (D4 - 64)) b2 = s_iv[lane + 64];

        float d = a0.x * b0.x + a0.y * b0.y + a0.z * b0.z + a0.w * b0.w;
        d += a1.x * b1.x + a1.y * b1.y + a1.z * b1.z + a1.w * b1.w;
        d += a2.x * b2.x + a2.y * b2.y + a2.z * b2.z + a2.w * b2.w;

        // Warp butterfly reduction (result broadcast to all lanes)
        #pragma unroll
        for (int off = 16; off > 0; off >>= 1)
            d += __shfl_xor_sync(0xffffffffu, d, off);

        // Positives: log_sigmoid(score)/20.  Negatives: score negated (n_vec = -o_emb),
        // and mean over 2W=10 after summing NEG -> /10.
        if (is_pos) acc += log_sigmoid_f(d)  * (1.0f / (float)N_OUT);
        else        acc += log_sigmoid_f(-d) * 0.1f;
    }

    if (lane == 0) s_warp[w] = acc;
    __syncthreads();

    if (tid == 0) {
        float s = 0.0f;
        #pragma unroll
        for (int i = 0; i < NWARPS; i++) s += s_warp[i];
        g_partial[b] = s;
    }
}

__global__ __launch_bounds__(THREADS)
void w2v_reduce_kernel(float* __restrict__ out)
{
    __shared__ float s_warp[NWARPS];
    const int tid  = threadIdx.x;
    const int lane = tid & 31;
    const int w    = tid >> 5;

    float sum = 0.0f;
    #pragma unroll 8
    for (int i = tid; i < BATCH; i += THREADS) sum += g_partial[i];

    #pragma unroll
    for (int off = 16; off > 0; off >>= 1)
        sum += __shfl_xor_sync(0xffffffffu, sum, off);

    if (lane == 0) s_warp[w] = sum;
    __syncthreads();

    if (tid == 0) {
        float total = 0.0f;
        #pragma unroll
        for (int i = 0; i < NWARPS; i++) total += s_warp[i];
        out[0] = -total / (float)BATCH;
    }
}

extern "C" void kernel_launch(void* const* d_in, const int* in_sizes, int n_in,
                              void* d_out, int out_size)
{
    const float* i_emb  = (const float*)d_in[0];
    const float* o_emb  = (const float*)d_in[1];
    const int*   i_word = (const int*)d_in[2];
    const int*   o_word = (const int*)d_in[3];
    const int*   n_word = (const int*)d_in[4];
    float* out = (float*)d_out;

    w2v_loss_kernel<<<BATCH, THREADS>>>(i_emb, o_emb, i_word, o_word, n_word);
    w2v_reduce_kernel<<<1, THREADS>>>(out);
}